// round 1
// baseline (speedup 1.0000x reference)
#include <cuda_runtime.h>
#include <cuda_bf16.h>
#include <math.h>

// ---------------------------------------------------------------------------
// TelephoneAttentionND  (B=2, L=2048, C=1024, H=16, D=64, K=64, S=33)
// Stage 1: wave(32)+exp(1) projections + activations  -> freq/phase/expo
// Stage 2: kern GEMM 4096x1024x1024 (+bias)           -> g_proj
// Stage 3: rmsnorm(1024)+silu                          -> g_kmax
// Stage 4: gather/interp/einsum attention              -> g_hidden
// Stage 5: out GEMM 4096x1024x1024 + silu              -> d_out
// ---------------------------------------------------------------------------

#define BATCH 2
#define SEQLEN 2048
#define CH 1024
#define NHEAD 16
#define HDIM 64
#define KSIZE 64
#define TOKENS (BATCH * SEQLEN)   // 4096

// scratch (device globals; no allocation allowed)
__device__ float g_freq[TOKENS * NHEAD];
__device__ float g_phase[TOKENS * NHEAD];
__device__ float g_expo[TOKENS];
__device__ float g_proj[(size_t)TOKENS * CH];
__device__ float g_kmax[(size_t)TOKENS * CH];
__device__ float g_hidden[(size_t)TOKENS * CH];

__device__ __forceinline__ float siluf(float v) {
    return v / (1.0f + expf(-v));
}

// ---------------------------------------------------------------------------
// Stage 1: per-token wave (32 outputs) + exp (1 output) projections.
// 128 threads/block, 1 block/token. x row cached in smem.
// ---------------------------------------------------------------------------
__global__ __launch_bounds__(128) void proj_small_kernel(
    const float* __restrict__ x,
    const float* __restrict__ w_wave, const float* __restrict__ b_wave,
    const float* __restrict__ g_wave,
    const float* __restrict__ w_exp, const float* __restrict__ b_exp,
    const float* __restrict__ g_exp)
{
    const int token = blockIdx.x;
    __shared__ float xs[CH];
    __shared__ float proj[33];

    const int tid  = threadIdx.x;
    const int wid  = tid >> 5;
    const int lane = tid & 31;

    const float* xrow = x + (size_t)token * CH;
    #pragma unroll
    for (int i = tid; i < CH; i += 128) xs[i] = xrow[i];
    __syncthreads();

    for (int o = wid; o < 33; o += 4) {
        const float* wrow = (o < 32) ? (w_wave + (size_t)o * CH) : w_exp;
        float sum = 0.0f;
        for (int i = lane; i < CH; i += 32) sum += xs[i] * wrow[i];
        #pragma unroll
        for (int d = 16; d > 0; d >>= 1) sum += __shfl_xor_sync(0xffffffffu, sum, d);
        if (lane == 0) proj[o] = sum + ((o < 32) ? b_wave[o] : b_exp[0]);
    }
    __syncthreads();

    if (tid < 32) {
        // rmsnorm over 32-wide wave vector, then silu
        float v  = proj[tid];
        float sq = v * v;
        #pragma unroll
        for (int d = 16; d > 0; d >>= 1) sq += __shfl_xor_sync(0xffffffffu, sq, d);
        float var = sq * (1.0f / 32.0f);
        float r   = rsqrtf(var + 1e-6f);
        float y   = g_wave[tid] * v * r;
        float sil = siluf(y);
        if (tid < 16) {
            // freq = sigmoid(wave0) * 15 + 1
            g_freq[(size_t)token * NHEAD + tid] =
                15.0f / (1.0f + expf(-sil)) + 1.0f;
        } else {
            // phase = tanh(wave1) * 16
            g_phase[(size_t)token * NHEAD + (tid - 16)] = tanhf(sil) * 16.0f;
        }
    } else if (tid == 32) {
        // exponent = sigmoid(rmsnorm_1(v)) * 3.5 + 0.5
        float v = proj[32];
        float y = g_exp[0] * v * rsqrtf(v * v + 1e-6f);
        float s = 1.0f / (1.0f + expf(-y));
        g_expo[token] = s * 3.5f + 0.5f;
    }
}

// ---------------------------------------------------------------------------
// Stages 2 & 5: 128x128x16 tiled SIMT fp32 GEMM, C = A[M,K] * B[N,K]^T.
// 256 threads, 8x8 micro-tile per thread. Optional bias + silu epilogue.
// M=4096, N=1024, K=1024 (all tile-divisible, no bounds checks).
// ---------------------------------------------------------------------------
#define GBM 128
#define GBN 128
#define GBK 16
#define GPAD 4

template <bool BIAS, bool SILU>
__global__ __launch_bounds__(256) void gemm_kernel(
    const float* __restrict__ A, const float* __restrict__ B,
    const float* __restrict__ bias, float* __restrict__ C,
    int M, int N, int Kdim)
{
    __shared__ float As[GBK][GBM + GPAD];
    __shared__ float Bs[GBK][GBN + GPAD];

    const int tid  = threadIdx.x;
    const int bm   = blockIdx.y * GBM;
    const int bn   = blockIdx.x * GBN;
    const int lrow = tid >> 2;          // 0..63
    const int lcol = (tid & 3) << 2;    // 0,4,8,12
    const int ty   = tid >> 4;          // 0..15
    const int tx   = tid & 15;          // 0..15

    float acc[8][8];
    #pragma unroll
    for (int i = 0; i < 8; i++)
        #pragma unroll
        for (int j = 0; j < 8; j++) acc[i][j] = 0.0f;

    for (int k0 = 0; k0 < Kdim; k0 += GBK) {
        #pragma unroll
        for (int half = 0; half < 2; half++) {
            const int r = lrow + half * 64;
            const float4 va = *(const float4*)(A + (size_t)(bm + r) * Kdim + k0 + lcol);
            As[lcol + 0][r] = va.x; As[lcol + 1][r] = va.y;
            As[lcol + 2][r] = va.z; As[lcol + 3][r] = va.w;
            const float4 vb = *(const float4*)(B + (size_t)(bn + r) * Kdim + k0 + lcol);
            Bs[lcol + 0][r] = vb.x; Bs[lcol + 1][r] = vb.y;
            Bs[lcol + 2][r] = vb.z; Bs[lcol + 3][r] = vb.w;
        }
        __syncthreads();

        #pragma unroll
        for (int k = 0; k < GBK; k++) {
            float a[8], b[8];
            *(float4*)&a[0] = *(const float4*)&As[k][ty * 8];
            *(float4*)&a[4] = *(const float4*)&As[k][ty * 8 + 4];
            *(float4*)&b[0] = *(const float4*)&Bs[k][tx * 8];
            *(float4*)&b[4] = *(const float4*)&Bs[k][tx * 8 + 4];
            #pragma unroll
            for (int i = 0; i < 8; i++)
                #pragma unroll
                for (int j = 0; j < 8; j++)
                    acc[i][j] += a[i] * b[j];
        }
        __syncthreads();
    }

    #pragma unroll
    for (int i = 0; i < 8; i++) {
        const size_t row = (size_t)(bm + ty * 8 + i);
        float* crow = C + row * N + bn + tx * 8;
        #pragma unroll
        for (int jc = 0; jc < 2; jc++) {
            float4 v;
            float t[4];
            #pragma unroll
            for (int j = 0; j < 4; j++) {
                float u = acc[i][jc * 4 + j];
                if (BIAS) u += bias[bn + tx * 8 + jc * 4 + j];
                if (SILU) u = siluf(u);
                t[j] = u;
            }
            v.x = t[0]; v.y = t[1]; v.z = t[2]; v.w = t[3];
            *(float4*)(crow + jc * 4) = v;
        }
    }
}

// ---------------------------------------------------------------------------
// Stage 3: rmsnorm over 1024 + g_kern scale + silu.
// ---------------------------------------------------------------------------
__global__ __launch_bounds__(256) void rmsnorm_silu_kernel(
    const float* __restrict__ gk)
{
    const int token = blockIdx.x;
    const float* p = g_proj + (size_t)token * CH;
    float* o = g_kmax + (size_t)token * CH;

    __shared__ float red[8];
    __shared__ float rbc;
    const int tid  = threadIdx.x;
    const int wid  = tid >> 5;
    const int lane = tid & 31;

    float sq = 0.0f;
    #pragma unroll
    for (int i = tid; i < CH; i += 256) { float v = p[i]; sq += v * v; }
    #pragma unroll
    for (int d = 16; d > 0; d >>= 1) sq += __shfl_xor_sync(0xffffffffu, sq, d);
    if (lane == 0) red[wid] = sq;
    __syncthreads();
    if (tid == 0) {
        float s = 0.0f;
        #pragma unroll
        for (int i = 0; i < 8; i++) s += red[i];
        rbc = rsqrtf(s * (1.0f / (float)CH) + 1e-6f);
    }
    __syncthreads();
    const float r = rbc;
    #pragma unroll
    for (int i = tid; i < CH; i += 256) {
        float y = gk[i] * p[i] * r;
        o[i] = siluf(y);
    }
}

// ---------------------------------------------------------------------------
// Stage 4: telephone attention gather + einsum.
// 1 block/token, 512 threads = 16 warps = 1 warp/head; lane covers 2 of D=64.
// ---------------------------------------------------------------------------
__global__ __launch_bounds__(512) void attn_kernel(const float* __restrict__ x)
{
    const int token = blockIdx.x;
    const int b = token >> 11;             // /SEQLEN
    const int l = token & (SEQLEN - 1);
    const int h    = threadIdx.x >> 5;
    const int lane = threadIdx.x & 31;

    __shared__ float km[NHEAD][KSIZE];
    const float* kr = g_kmax + (size_t)token * CH;
    km[h][lane]      = kr[h * KSIZE + lane];
    km[h][lane + 32] = kr[h * KSIZE + lane + 32];
    __syncthreads();

    const float f = g_freq[(size_t)token * NHEAD + h];
    const float p = g_phase[(size_t)token * NHEAD + h];
    const float e = g_expo[token];

    const float* xb = x + (size_t)b * SEQLEN * CH + h * HDIM;

    float acc0 = 0.0f, acc1 = 0.0f;
    #pragma unroll 1
    for (int s = 0; s < 33; s++) {
        const float off = (float)(s - 16);
        const float rel = off * f;
        const float pos = (float)l + rel + p;
        const float validf = (pos >= 0.0f && pos < (float)SEQLEN) ? 1.0f : 0.0f;
        float pc = fminf(fmaxf(pos, 0.0f), (float)SEQLEN - 1.001f);
        const int   fl   = (int)floorf(pc);       // in [0, L-2]
        const float frac = pc - (float)fl;

        const float ar   = fabsf(rel);
        const float powr = expf(-e * log1pf(ar * (1.0f / (float)SEQLEN)));
        const float idxf = fminf(ar * (1.0f / 256.0f), 1.0f) * 63.0f;
        int   i0 = (int)idxf; if (i0 > 62) i0 = 62;
        const float wc = idxf - (float)i0;
        const float kern = (km[h][i0] * (1.0f - wc) + km[h][i0 + 1] * wc) * powr * validf;

        const float* vfp = xb + (size_t)fl * CH;
        const float* vcp = vfp + CH;   // cl = fl + 1 (fl <= L-2)
        const float vflo0 = vfp[lane];
        const float vflo1 = vfp[lane + 32];
        const float v0 = vflo0 + frac * (vcp[lane]      - vflo0);
        const float v1 = vflo1 + frac * (vcp[lane + 32] - vflo1);
        acc0 += kern * v0;
        acc1 += kern * v1;
    }

    float* hp = g_hidden + (size_t)token * CH + h * HDIM;
    hp[lane]      = acc0;
    hp[lane + 32] = acc1;
}

// ---------------------------------------------------------------------------
// launch
// ---------------------------------------------------------------------------
extern "C" void kernel_launch(void* const* d_in, const int* in_sizes, int n_in,
                              void* d_out, int out_size)
{
    const float* x      = (const float*)d_in[0];
    const float* w_wave = (const float*)d_in[1];
    const float* b_wave = (const float*)d_in[2];
    const float* g_wave = (const float*)d_in[3];
    const float* w_kern = (const float*)d_in[4];
    const float* b_kern = (const float*)d_in[5];
    const float* g_kern = (const float*)d_in[6];
    const float* w_exp  = (const float*)d_in[7];
    const float* b_exp  = (const float*)d_in[8];
    const float* g_exp  = (const float*)d_in[9];
    const float* w_out  = (const float*)d_in[10];
    float* out = (float*)d_out;

    float *proj_ptr, *hidden_ptr;
    cudaGetSymbolAddress((void**)&proj_ptr,   g_proj);
    cudaGetSymbolAddress((void**)&hidden_ptr, g_hidden);

    // Stage 1: wave + exp projections
    proj_small_kernel<<<TOKENS, 128>>>(x, w_wave, b_wave, g_wave,
                                       w_exp, b_exp, g_exp);

    // Stage 2: kern projection GEMM (+bias, raw)
    dim3 ggrid(CH / GBN, TOKENS / GBM);
    gemm_kernel<true, false><<<ggrid, 256>>>(x, w_kern, b_kern, proj_ptr,
                                             TOKENS, CH, CH);

    // Stage 3: rmsnorm + silu -> kernel_max
    rmsnorm_silu_kernel<<<TOKENS, 256>>>(g_kern);

    // Stage 4: gather / interpolate / einsum -> hidden
    attn_kernel<<<TOKENS, 512>>>(x);

    // Stage 5: output GEMM + silu
    gemm_kernel<false, true><<<ggrid, 256>>>(hidden_ptr, w_out, nullptr, out,
                                             TOKENS, CH, CH);
}

// round 3
// speedup vs baseline: 2.0393x; 2.0393x over previous
#include <cuda_runtime.h>
#include <cuda_bf16.h>
#include <cstdint>
#include <math.h>

// ---------------------------------------------------------------------------
// TelephoneAttentionND  (B=2, L=2048, C=1024, H=16, D=64, K=64, S=33)
// Stage 1: tiled wave(32)+exp(1) projection + activations -> freq/phase/expo
// Stage 2: kern GEMM 4096x1024x1024 (+bias) [mma.sync tf32] -> g_proj
// Stage 3: rmsnorm(1024)+silu                               -> g_kmax
// Stage 4: gather/interp/einsum attention (2-phase)         -> g_hidden
// Stage 5: out GEMM 4096x1024x1024 + silu   [mma.sync tf32] -> d_out
// ---------------------------------------------------------------------------

#define BATCH 2
#define SEQLEN 2048
#define CH 1024
#define NHEAD 16
#define HDIM 64
#define KSIZE 64
#define TOKENS (BATCH * SEQLEN)   // 4096

// scratch (device globals; no allocation allowed)
__device__ float g_freq[TOKENS * NHEAD];
__device__ float g_phase[TOKENS * NHEAD];
__device__ float g_expo[TOKENS];
__device__ float g_proj[(size_t)TOKENS * CH];
__device__ float g_kmax[(size_t)TOKENS * CH];
__device__ float g_hidden[(size_t)TOKENS * CH];

__device__ __forceinline__ float siluf(float v) {
    return v / (1.0f + expf(-v));
}

__device__ __forceinline__ uint32_t f2tf32(float x) {
    uint32_t r;
    asm("cvt.rna.tf32.f32 %0, %1;" : "=r"(r) : "f"(x));
    return r;
}

__device__ __forceinline__ void mma_tf32_16x8x8(
    float c[4], const uint32_t a[4], const uint32_t b[2])
{
    asm volatile(
        "mma.sync.aligned.m16n8k8.row.col.f32.tf32.tf32.f32 "
        "{%0, %1, %2, %3}, {%4, %5, %6, %7}, {%8, %9}, {%0, %1, %2, %3};"
        : "+f"(c[0]), "+f"(c[1]), "+f"(c[2]), "+f"(c[3])
        : "r"(a[0]), "r"(a[1]), "r"(a[2]), "r"(a[3]), "r"(b[0]), "r"(b[1]));
}

// ===========================================================================
// Stage 1: tiled wave+exp projection. 128 blocks x 32 tokens, 256 threads.
// ===========================================================================
__global__ __launch_bounds__(256) void proj_small_kernel(
    const float* __restrict__ x,
    const float* __restrict__ w_wave, const float* __restrict__ b_wave,
    const float* __restrict__ g_wave,
    const float* __restrict__ w_exp, const float* __restrict__ b_exp,
    const float* __restrict__ g_exp)
{
    const int t0 = blockIdx.x * 32;
    __shared__ float xs[32][33];   // [k][token]
    __shared__ float ws[32][34];   // [k][o] (33 outputs)
    __shared__ float po[32][34];   // [token][o]

    const int tid = threadIdx.x;
    const int tt  = tid & 31;      // token within block
    const int og  = tid >> 5;      // output group 0..7
    const int obase = og * 4;
    const bool five = (og == 7);   // group 7 also handles o=32 (exp)

    float acc[5] = {0.f, 0.f, 0.f, 0.f, 0.f};

    for (int k0 = 0; k0 < CH; k0 += 32) {
        {
            const int token = tid >> 3, c4 = tid & 7;
            const float4 v = *(const float4*)(x + (size_t)(t0 + token) * CH + k0 + c4 * 4);
            xs[c4 * 4 + 0][token] = v.x; xs[c4 * 4 + 1][token] = v.y;
            xs[c4 * 4 + 2][token] = v.z; xs[c4 * 4 + 3][token] = v.w;
        }
        for (int fi = tid; fi < 33 * 8; fi += 256) {
            const int o = fi >> 3, c4 = fi & 7;
            const float* wr = (o < 32) ? (w_wave + (size_t)o * CH) : w_exp;
            const float4 v = *(const float4*)(wr + k0 + c4 * 4);
            ws[c4 * 4 + 0][o] = v.x; ws[c4 * 4 + 1][o] = v.y;
            ws[c4 * 4 + 2][o] = v.z; ws[c4 * 4 + 3][o] = v.w;
        }
        __syncthreads();
        #pragma unroll
        for (int k = 0; k < 32; k++) {
            const float xv = xs[k][tt];
            acc[0] += xv * ws[k][obase + 0];
            acc[1] += xv * ws[k][obase + 1];
            acc[2] += xv * ws[k][obase + 2];
            acc[3] += xv * ws[k][obase + 3];
            if (five) acc[4] += xv * ws[k][32];
        }
        __syncthreads();
    }

    po[tt][obase + 0] = acc[0] + b_wave[obase + 0];
    po[tt][obase + 1] = acc[1] + b_wave[obase + 1];
    po[tt][obase + 2] = acc[2] + b_wave[obase + 2];
    po[tt][obase + 3] = acc[3] + b_wave[obase + 3];
    if (five) po[tt][32] = acc[4] + b_exp[0];
    __syncthreads();

    // activations: 8 warps x 4 rounds cover 32 tokens
    const int wid = tid >> 5, lane = tid & 31;
    for (int it = 0; it < 4; it++) {
        const int tk = wid * 4 + it;
        const int gtok = t0 + tk;
        float v = po[tk][lane];
        float sq = v * v;
        #pragma unroll
        for (int d = 16; d > 0; d >>= 1) sq += __shfl_xor_sync(0xffffffffu, sq, d);
        const float r = rsqrtf(sq * (1.0f / 32.0f) + 1e-6f);
        const float sil = siluf(g_wave[lane] * v * r);
        if (lane < 16) {
            g_freq[(size_t)gtok * NHEAD + lane] = 15.0f / (1.0f + expf(-sil)) + 1.0f;
        } else {
            g_phase[(size_t)gtok * NHEAD + (lane - 16)] = tanhf(sil) * 16.0f;
        }
        if (lane == 0) {
            const float ve = po[tk][32];
            const float y = g_exp[0] * ve * rsqrtf(ve * ve + 1e-6f);
            g_expo[gtok] = (1.0f / (1.0f + expf(-y))) * 3.5f + 0.5f;
        }
    }
}

// ===========================================================================
// Stages 2 & 5: tf32 mma.sync GEMM, C[M,N] = A[M,K] * B[N,K]^T.
// 128x128 CTA tile, 8 warps (2x4), each warp 64x32 via 4x4 m16n8k8 tiles.
// BK=16, double-buffered smem, register-prefetch of next chunk.
// smem row stride 20 floats -> conflict-free fragment loads.
// ===========================================================================
#define GSTRIDE 20

template <bool BIAS, bool SILU>
__global__ __launch_bounds__(256) void gemm_tc_kernel(
    const float* __restrict__ A, const float* __restrict__ B,
    const float* __restrict__ bias, float* __restrict__ C)
{
    __shared__ uint32_t As[2][128][GSTRIDE];
    __shared__ uint32_t Bs[2][128][GSTRIDE];

    const int tid  = threadIdx.x;
    const int wid  = tid >> 5;
    const int lane = tid & 31;
    const int gid  = lane >> 2;     // groupID 0..7
    const int tig  = lane & 3;      // thread-in-group 0..3
    const int wm   = wid & 1;       // warp row (0..1) -> 64 rows each
    const int wn   = wid >> 1;      // warp col (0..3) -> 32 cols each

    const int bm = blockIdx.y * 128;
    const int bn = blockIdx.x * 128;
    const float* gA = A + (size_t)bm * CH;
    const float* gB = B + (size_t)bn * CH;

    // global-load mapping: 512 float4 per matrix per chunk; 2 per thread.
    const int r0 = (tid + 0)   >> 2, c0 = ((tid + 0)   & 3) * 4;
    const int r1 = (tid + 256) >> 2, c1 = ((tid + 256) & 3) * 4;

    float c[4][4][4];
    #pragma unroll
    for (int mt = 0; mt < 4; mt++)
        #pragma unroll
        for (int nt = 0; nt < 4; nt++)
            #pragma unroll
            for (int j = 0; j < 4; j++) c[mt][nt][j] = 0.0f;

    // prologue: load chunk 0 into buf 0
    {
        const float4 va0 = *(const float4*)(gA + (size_t)r0 * CH + c0);
        const float4 va1 = *(const float4*)(gA + (size_t)r1 * CH + c1);
        const float4 vb0 = *(const float4*)(gB + (size_t)r0 * CH + c0);
        const float4 vb1 = *(const float4*)(gB + (size_t)r1 * CH + c1);
        As[0][r0][c0+0]=f2tf32(va0.x); As[0][r0][c0+1]=f2tf32(va0.y);
        As[0][r0][c0+2]=f2tf32(va0.z); As[0][r0][c0+3]=f2tf32(va0.w);
        As[0][r1][c1+0]=f2tf32(va1.x); As[0][r1][c1+1]=f2tf32(va1.y);
        As[0][r1][c1+2]=f2tf32(va1.z); As[0][r1][c1+3]=f2tf32(va1.w);
        Bs[0][r0][c0+0]=f2tf32(vb0.x); Bs[0][r0][c0+1]=f2tf32(vb0.y);
        Bs[0][r0][c0+2]=f2tf32(vb0.z); Bs[0][r0][c0+3]=f2tf32(vb0.w);
        Bs[0][r1][c1+0]=f2tf32(vb1.x); Bs[0][r1][c1+1]=f2tf32(vb1.y);
        Bs[0][r1][c1+2]=f2tf32(vb1.z); Bs[0][r1][c1+3]=f2tf32(vb1.w);
    }
    __syncthreads();

    const int NCHUNK = CH / 16;   // 64
    for (int kc = 0; kc < NCHUNK; kc++) {
        const int buf = kc & 1;

        float4 pa0, pa1, pb0, pb1;
        if (kc + 1 < NCHUNK) {
            const int k0 = (kc + 1) * 16;
            pa0 = *(const float4*)(gA + (size_t)r0 * CH + k0 + c0);
            pa1 = *(const float4*)(gA + (size_t)r1 * CH + k0 + c1);
            pb0 = *(const float4*)(gB + (size_t)r0 * CH + k0 + c0);
            pb1 = *(const float4*)(gB + (size_t)r1 * CH + k0 + c1);
        }

        #pragma unroll
        for (int ks = 0; ks < 2; ks++) {
            const int kb = ks * 8 + tig;
            uint32_t a[4][4], b[4][2];
            #pragma unroll
            for (int mt = 0; mt < 4; mt++) {
                const int row = wm * 64 + mt * 16 + gid;
                a[mt][0] = As[buf][row][kb];
                a[mt][1] = As[buf][row + 8][kb];
                a[mt][2] = As[buf][row][kb + 4];
                a[mt][3] = As[buf][row + 8][kb + 4];
            }
            #pragma unroll
            for (int nt = 0; nt < 4; nt++) {
                const int n = wn * 32 + nt * 8 + gid;
                b[nt][0] = Bs[buf][n][kb];
                b[nt][1] = Bs[buf][n][kb + 4];
            }
            #pragma unroll
            for (int mt = 0; mt < 4; mt++)
                #pragma unroll
                for (int nt = 0; nt < 4; nt++)
                    mma_tf32_16x8x8(c[mt][nt], a[mt], b[nt]);
        }

        if (kc + 1 < NCHUNK) {
            const int nb = (kc + 1) & 1;
            __syncthreads();
            As[nb][r0][c0+0]=f2tf32(pa0.x); As[nb][r0][c0+1]=f2tf32(pa0.y);
            As[nb][r0][c0+2]=f2tf32(pa0.z); As[nb][r0][c0+3]=f2tf32(pa0.w);
            As[nb][r1][c1+0]=f2tf32(pa1.x); As[nb][r1][c1+1]=f2tf32(pa1.y);
            As[nb][r1][c1+2]=f2tf32(pa1.z); As[nb][r1][c1+3]=f2tf32(pa1.w);
            Bs[nb][r0][c0+0]=f2tf32(pb0.x); Bs[nb][r0][c0+1]=f2tf32(pb0.y);
            Bs[nb][r0][c0+2]=f2tf32(pb0.z); Bs[nb][r0][c0+3]=f2tf32(pb0.w);
            Bs[nb][r1][c1+0]=f2tf32(pb1.x); Bs[nb][r1][c1+1]=f2tf32(pb1.y);
            Bs[nb][r1][c1+2]=f2tf32(pb1.z); Bs[nb][r1][c1+3]=f2tf32(pb1.w);
            __syncthreads();
        }
    }

    // epilogue: c0,c1 at (row, col..col+1); c2,c3 at (row+8, col..col+1)
    #pragma unroll
    for (int mt = 0; mt < 4; mt++) {
        const int row = bm + wm * 64 + mt * 16 + gid;
        #pragma unroll
        for (int nt = 0; nt < 4; nt++) {
            const int col = bn + wn * 32 + nt * 8 + tig * 2;
            float u0 = c[mt][nt][0], u1 = c[mt][nt][1];
            float u2 = c[mt][nt][2], u3 = c[mt][nt][3];
            if (BIAS) {
                const float b0v = bias[col], b1v = bias[col + 1];
                u0 += b0v; u1 += b1v; u2 += b0v; u3 += b1v;
            }
            if (SILU) {
                u0 = siluf(u0); u1 = siluf(u1); u2 = siluf(u2); u3 = siluf(u3);
            }
            *(float2*)(C + (size_t)row * CH + col)       = make_float2(u0, u1);
            *(float2*)(C + (size_t)(row + 8) * CH + col) = make_float2(u2, u3);
        }
    }
}

// ===========================================================================
// Stage 3: rmsnorm over 1024 + g_kern scale + silu.
// ===========================================================================
__global__ __launch_bounds__(256) void rmsnorm_silu_kernel(
    const float* __restrict__ gk)
{
    const int token = blockIdx.x;
    const float* p = g_proj + (size_t)token * CH;
    float* o = g_kmax + (size_t)token * CH;

    __shared__ float red[8];
    __shared__ float rbc;
    const int tid  = threadIdx.x;
    const int wid  = tid >> 5;
    const int lane = tid & 31;

    float sq = 0.0f;
    #pragma unroll
    for (int i = tid; i < CH; i += 256) { const float v = p[i]; sq += v * v; }
    #pragma unroll
    for (int d = 16; d > 0; d >>= 1) sq += __shfl_xor_sync(0xffffffffu, sq, d);
    if (lane == 0) red[wid] = sq;
    __syncthreads();
    if (tid == 0) {
        float s = 0.0f;
        #pragma unroll
        for (int i = 0; i < 8; i++) s += red[i];
        rbc = rsqrtf(s * (1.0f / (float)CH) + 1e-6f);
    }
    __syncthreads();
    const float r = rbc;
    #pragma unroll
    for (int i = tid; i < CH; i += 256) {
        o[i] = siluf(gk[i] * p[i] * r);
    }
}

// ===========================================================================
// Stage 4: telephone attention. 1 block/token, 16 warps (1/head).
// Phase A: lane s computes sample-s scalars once. Phase B: lean gather loop.
// ===========================================================================
__global__ __launch_bounds__(512) void attn_kernel(const float* __restrict__ x)
{
    const int token = blockIdx.x;
    const int b = token >> 11;
    const int l = token & (SEQLEN - 1);
    const int h    = threadIdx.x >> 5;
    const int lane = threadIdx.x & 31;

    __shared__ float km[NHEAD][KSIZE];
    __shared__ float skern[NHEAD][33];
    __shared__ float sfrac[NHEAD][33];
    __shared__ int   sfl[NHEAD][33];

    const float* kr = g_kmax + (size_t)token * CH;
    km[h][lane]      = kr[h * KSIZE + lane];
    km[h][lane + 32] = kr[h * KSIZE + lane + 32];

    const float f = g_freq[(size_t)token * NHEAD + h];
    const float p = g_phase[(size_t)token * NHEAD + h];
    const float e = g_expo[token];
    __syncwarp();

    // Phase A: per-sample scalars (lane-parallel)
    for (int s = lane; s < 33; s += 32) {
        const float off = (float)(s - 16);
        const float rel = off * f;
        const float pos = (float)l + rel + p;
        const float validf = (pos >= 0.0f && pos < (float)SEQLEN) ? 1.0f : 0.0f;
        const float pc = fminf(fmaxf(pos, 0.0f), (float)SEQLEN - 1.001f);
        const int   fl = (int)floorf(pc);
        const float frac = pc - (float)fl;
        const float ar = fabsf(rel);
        const float powr = expf(-e * log1pf(ar * (1.0f / (float)SEQLEN)));
        const float idxf = fminf(ar * (1.0f / 256.0f), 1.0f) * 63.0f;
        int i0 = (int)idxf; if (i0 > 62) i0 = 62;
        const float wc = idxf - (float)i0;
        skern[h][s] = (km[h][i0] * (1.0f - wc) + km[h][i0 + 1] * wc) * powr * validf;
        sfrac[h][s] = frac;
        sfl[h][s]   = fl;
    }
    __syncwarp();

    // Phase B: gather + interpolate + accumulate. lane covers d=2*lane..2*lane+1.
    const float2* xb = (const float2*)(x + ((size_t)b * SEQLEN) * CH + h * HDIM);
    float acc0 = 0.0f, acc1 = 0.0f;
    #pragma unroll 3
    for (int s = 0; s < 33; s++) {
        const float kern = skern[h][s];
        const float frac = sfrac[h][s];
        const float2* vfp = xb + (size_t)sfl[h][s] * (CH / 2);
        const float2 vf = vfp[lane];
        const float2 vc = vfp[CH / 2 + lane];
        acc0 += kern * (vf.x + frac * (vc.x - vf.x));
        acc1 += kern * (vf.y + frac * (vc.y - vf.y));
    }

    float2* hp = (float2*)(g_hidden + (size_t)token * CH + h * HDIM);
    hp[lane] = make_float2(acc0, acc1);
}

// ===========================================================================
// launch
// ===========================================================================
extern "C" void kernel_launch(void* const* d_in, const int* in_sizes, int n_in,
                              void* d_out, int out_size)
{
    const float* x      = (const float*)d_in[0];
    const float* w_wave = (const float*)d_in[1];
    const float* b_wave = (const float*)d_in[2];
    const float* g_wave = (const float*)d_in[3];
    const float* w_kern = (const float*)d_in[4];
    const float* b_kern = (const float*)d_in[5];
    const float* g_kern = (const float*)d_in[6];
    const float* w_exp  = (const float*)d_in[7];
    const float* b_exp  = (const float*)d_in[8];
    const float* g_exp  = (const float*)d_in[9];
    const float* w_out  = (const float*)d_in[10];
    float* out = (float*)d_out;

    float *proj_ptr, *hidden_ptr;
    cudaGetSymbolAddress((void**)&proj_ptr,   g_proj);
    cudaGetSymbolAddress((void**)&hidden_ptr, g_hidden);

    // Stage 1: wave + exp projections (tiled)
    proj_small_kernel<<<TOKENS / 32, 256>>>(x, w_wave, b_wave, g_wave,
                                            w_exp, b_exp, g_exp);

    // Stage 2: kern projection GEMM (+bias) via tf32 mma.sync
    dim3 ggrid(CH / 128, TOKENS / 128);   // (8, 32)
    gemm_tc_kernel<true, false><<<ggrid, 256>>>(x, w_kern, b_kern, proj_ptr);

    // Stage 3: rmsnorm + silu -> kernel_max
    rmsnorm_silu_kernel<<<TOKENS, 256>>>(g_kern);

    // Stage 4: gather / interpolate / einsum -> hidden
    attn_kernel<<<TOKENS, 512>>>(x);

    // Stage 5: output GEMM + silu via tf32 mma.sync
    gemm_tc_kernel<false, true><<<ggrid, 256>>>(hidden_ptr, w_out, nullptr, out);
}